// round 15
// baseline (speedup 1.0000x reference)
#include <cuda_runtime.h>
#include <cuda_fp16.h>

#define N_NODES 100000
#define MAX_E   1600000
#define D 64
#define SCAN_B 1024

struct Edge { int s; float nrm; };

// Scratch (allocation-free rule).
__device__ __align__(256) __half g_xh [N_NODES * D];  // fp16 copy of input x
__device__ __align__(256) __half g_hh [N_NODES * D];  // fp16 gemm output (gather source)
__device__ __align__(256) __half g_th0[N_NODES * D];  // fp16 layer-0 activations
__device__ __align__(256) __half g_th1[N_NODES * D];  // fp16 layer-1 activations
__device__ int   g_deg [N_NODES];
__device__ int   g_fill[N_NODES];
__device__ int   g_rowp[N_NODES];
__device__ float g_dinv[N_NODES];
__device__ int   g_bsum[256];
__device__ __align__(16) Edge g_csr[MAX_E];

// x(fp32) -> xh(fp16), vectorized 8 elements/thread
__global__ void k_cvt(const float* __restrict__ x, __half* __restrict__ xh, int n8) {
    int i = blockIdx.x * blockDim.x + threadIdx.x;
    if (i >= n8) return;
    const float4* x4 = (const float4*)x;
    float4 f0 = x4[i * 2], f1 = x4[i * 2 + 1];
    __half2 p0 = __floats2half2_rn(f0.x, f0.y);
    __half2 p1 = __floats2half2_rn(f0.z, f0.w);
    __half2 p2 = __floats2half2_rn(f1.x, f1.y);
    __half2 p3 = __floats2half2_rn(f1.z, f1.w);
    uint4 hv;
    hv.x = reinterpret_cast<unsigned&>(p0);
    hv.y = reinterpret_cast<unsigned&>(p1);
    hv.z = reinterpret_cast<unsigned&>(p2);
    hv.w = reinterpret_cast<unsigned&>(p3);
    ((uint4*)xh)[i] = hv;
}

__global__ void k_zero(int n) {
    int i = blockIdx.x * blockDim.x + threadIdx.x;
    if (i < n) { g_deg[i] = 0; g_fill[i] = 0; }
}

__global__ void k_count_deg(const int* __restrict__ dst, int e) {
    int i = blockIdx.x * blockDim.x + threadIdx.x;
    if (i < e) atomicAdd(&g_deg[dst[i]], 1);
}

// ---- exclusive scan of g_deg -> g_rowp ; also computes dinv (fused) ----
__global__ void k_scan_block(int n) {
    __shared__ int sm[SCAN_B];
    int t = threadIdx.x;
    int i = blockIdx.x * SCAN_B + t;
    int v = (i < n) ? g_deg[i] : 0;
    if (i < n) g_dinv[i] = rsqrtf((float)v + 1.0f);
    sm[t] = v;
    __syncthreads();
    #pragma unroll
    for (int off = 1; off < SCAN_B; off <<= 1) {
        int add = (t >= off) ? sm[t - off] : 0;
        __syncthreads();
        sm[t] += add;
        __syncthreads();
    }
    if (i < n) g_rowp[i] = sm[t] - v;
    if (t == SCAN_B - 1) g_bsum[blockIdx.x] = sm[t];
}

__global__ void k_scan_bsum(int nb) {
    if (nb > 256) nb = 256;
    int acc = 0;
    for (int b = 0; b < nb; b++) { int v = g_bsum[b]; g_bsum[b] = acc; acc += v; }
}

__global__ void k_scan_add(int n) {
    int i = blockIdx.x * blockDim.x + threadIdx.x;
    if (i < n) g_rowp[i] += g_bsum[i / SCAN_B];
}

__global__ void k_fill(const int* __restrict__ src, const int* __restrict__ dst, int e) {
    int i = blockIdx.x * blockDim.x + threadIdx.x;
    if (i >= e) return;
    int s = src[i], d = dst[i];
    int pos = g_rowp[d] + atomicAdd(&g_fill[d], 1);
    if (pos >= MAX_E) pos = MAX_E - 1;
    Edge ed; ed.s = s; ed.nrm = g_dinv[s] * g_dinv[d];
    g_csr[pos] = ed;
}

// GEMM: H(fp16) = (RELU? relu(A):A) @ W, A in fp16.
// 256 threads/block, 256 rows/block. Thread: 8 rows x 8 cols (64 acc regs).
template<bool RELU>
__global__ void __launch_bounds__(256, 2) k_gemm(
        const __half* __restrict__ A, const float* __restrict__ W,
        __half* __restrict__ Hh, int n) {
    __shared__ float4 Ws[1024];   // 64x64 W
    int tid = threadIdx.x;
    const float4* W4 = (const float4*)W;
    #pragma unroll
    for (int i = 0; i < 4; i++) Ws[tid + i * 256] = W4[tid + i * 256];
    __syncthreads();

    int cslice = tid & 7;
    int row0   = blockIdx.x * 256 + (tid >> 3) * 8;
    int c2     = cslice * 2;

    const uint4* Ar[8];
    #pragma unroll
    for (int rr = 0; rr < 8; rr++) {
        int r = row0 + rr; if (r >= n) r = n - 1;
        Ar[rr] = (const uint4*)A + (size_t)r * 8;
    }

    float acc[8][8];
    #pragma unroll
    for (int r = 0; r < 8; r++)
        #pragma unroll
        for (int c = 0; c < 8; c++) acc[r][c] = 0.0f;

    #pragma unroll
    for (int k8 = 0; k8 < 8; k8++) {
        uint4 av[8];
        #pragma unroll
        for (int rr = 0; rr < 8; rr++) av[rr] = Ar[rr][k8];
        #pragma unroll
        for (int j = 0; j < 8; j++) {
            int k = k8 * 8 + j;
            float4 w0 = Ws[k * 16 + c2];
            float4 w1 = Ws[k * 16 + c2 + 1];
            #pragma unroll
            for (int rr = 0; rr < 8; rr++) {
                float v = __half2float(((const __half*)&av[rr])[j]);
                if (RELU) v = fmaxf(v, 0.0f);
                acc[rr][0] += v * w0.x; acc[rr][1] += v * w0.y;
                acc[rr][2] += v * w0.z; acc[rr][3] += v * w0.w;
                acc[rr][4] += v * w1.x; acc[rr][5] += v * w1.y;
                acc[rr][6] += v * w1.z; acc[rr][7] += v * w1.w;
            }
        }
    }

    #pragma unroll
    for (int rr = 0; rr < 8; rr++) {
        int r = row0 + rr;
        if (r >= n) break;
        __half2 p0 = __floats2half2_rn(acc[rr][0], acc[rr][1]);
        __half2 p1 = __floats2half2_rn(acc[rr][2], acc[rr][3]);
        __half2 p2 = __floats2half2_rn(acc[rr][4], acc[rr][5]);
        __half2 p3 = __floats2half2_rn(acc[rr][6], acc[rr][7]);
        uint4 hv;
        hv.x = reinterpret_cast<unsigned&>(p0);
        hv.y = reinterpret_cast<unsigned&>(p1);
        hv.z = reinterpret_cast<unsigned&>(p2);
        hv.w = reinterpret_cast<unsigned&>(p3);
        ((uint4*)Hh)[(size_t)r * 8 + cslice] = hv;
    }
}

// Warp-per-node CSR gather + self-loop + bias.
// Lane l owns half2 column l (cols 2l, 2l+1). Per edge: one coalesced 128B row
// fetch by the warp. Edge records fetched 32-wide coalesced, shfl-broadcast.
template<bool OUT_HALF>
__global__ void __launch_bounds__(256) k_gather(const __half* __restrict__ Hh,
                                                const float* __restrict__ b,
                                                void* __restrict__ outv, int n) {
    int node = (blockIdx.x * blockDim.x + threadIdx.x) >> 5;
    if (node >= n) return;
    int lane = threadIdx.x & 31;

    int start = __ldg(&g_rowp[node]);
    int cnt   = __ldg(&g_deg[node]);
    float di  = __ldg(&g_dinv[node]);
    const Edge* ce = g_csr + start;
    const __half2* H2 = (const __half2*)Hh;

    float ax = 0.0f, ay = 0.0f;

    for (int base = 0; base < cnt; base += 32) {
        Edge my;
        int idx = base + lane;
        if (idx < cnt) my = ce[idx];
        else { my.s = node; my.nrm = 0.0f; }
        int m = min(32, cnt - base);
        int j = 0;
        for (; j + 4 <= m; j += 4) {
            int   s0 = __shfl_sync(0xffffffffu, my.s, j);
            int   s1 = __shfl_sync(0xffffffffu, my.s, j + 1);
            int   s2 = __shfl_sync(0xffffffffu, my.s, j + 2);
            int   s3 = __shfl_sync(0xffffffffu, my.s, j + 3);
            float n0 = __shfl_sync(0xffffffffu, my.nrm, j);
            float n1 = __shfl_sync(0xffffffffu, my.nrm, j + 1);
            float n2 = __shfl_sync(0xffffffffu, my.nrm, j + 2);
            float n3 = __shfl_sync(0xffffffffu, my.nrm, j + 3);
            __half2 h0 = H2[(size_t)s0 * 32 + lane];
            __half2 h1 = H2[(size_t)s1 * 32 + lane];
            __half2 h2 = H2[(size_t)s2 * 32 + lane];
            __half2 h3 = H2[(size_t)s3 * 32 + lane];
            float2 f0 = __half22float2(h0), f1 = __half22float2(h1);
            float2 f2 = __half22float2(h2), f3 = __half22float2(h3);
            ax += f0.x * n0; ay += f0.y * n0;
            ax += f1.x * n1; ay += f1.y * n1;
            ax += f2.x * n2; ay += f2.y * n2;
            ax += f3.x * n3; ay += f3.y * n3;
        }
        for (; j < m; j++) {
            int   s0 = __shfl_sync(0xffffffffu, my.s, j);
            float n0 = __shfl_sync(0xffffffffu, my.nrm, j);
            __half2 h0 = H2[(size_t)s0 * 32 + lane];
            float2 f0 = __half22float2(h0);
            ax += f0.x * n0; ay += f0.y * n0;
        }
    }

    // self-loop + bias
    float s = di * di;
    __half2 hs = H2[(size_t)node * 32 + lane];
    float2 fs = __half22float2(hs);
    float2 bb = __ldg((const float2*)b + lane);
    float o0 = ax + fs.x * s + bb.x;
    float o1 = ay + fs.y * s + bb.y;

    if (OUT_HALF) {
        ((__half2*)outv)[(size_t)node * 32 + lane] = __floats2half2_rn(o0, o1);
    } else {
        ((float2*)outv)[(size_t)node * 32 + lane] = make_float2(o0, o1);
    }
}

extern "C" void kernel_launch(void* const* d_in, const int* in_sizes, int n_in,
                              void* d_out, int out_size) {
    const float* x  = (const float*)d_in[0];
    const int*   ei = (const int*)d_in[1];   // int32 (JAX x64-disabled)
    const float* W0 = (const float*)d_in[2];
    const float* b0 = (const float*)d_in[3];
    const float* W1 = (const float*)d_in[4];
    const float* b1 = (const float*)d_in[5];
    const float* W2 = (const float*)d_in[6];
    const float* b2 = (const float*)d_in[7];
    float* out = (float*)d_out;

    int n = in_sizes[0] / D;
    int e = in_sizes[1] / 2;
    const int* src = ei;
    const int* dst = ei + e;

    __half *xh, *hh, *th0, *th1;
    cudaGetSymbolAddress((void**)&xh,  g_xh);
    cudaGetSymbolAddress((void**)&hh,  g_hh);
    cudaGetSymbolAddress((void**)&th0, g_th0);
    cudaGetSymbolAddress((void**)&th1, g_th1);

    const int TB = 256;
    int n8 = n * 8;
    int gb_n    = (n + TB - 1) / TB;
    int gb_e    = (e + TB - 1) / TB;
    int gb_gemm = (n + 255) / 256;
    int gb_cvt  = (n8 + TB - 1) / TB;
    int nb_scan = (n + SCAN_B - 1) / SCAN_B;
    int gb_ga   = (n + 7) / 8;            // 1 warp/node, 8 warps/block

    k_cvt<<<gb_cvt, TB>>>(x, xh, n8);                 // 0
    k_zero<<<gb_n, TB>>>(n);                          // 1
    k_count_deg<<<gb_e, TB>>>(dst, e);                // 2
    k_gemm<false><<<gb_gemm, TB>>>(xh, W0, hh, n);    // 3  <- profiled
    k_scan_block<<<nb_scan, SCAN_B>>>(n);             // 4 (also computes dinv)
    k_scan_bsum<<<1, 1>>>(nb_scan);                   // 5
    k_scan_add<<<gb_n, TB>>>(n);                      // 6
    k_fill<<<gb_e, TB>>>(src, dst, e);                // 7
    // layer 0 aggregate -> fp16 activations
    k_gather<true><<<gb_ga, TB>>>(hh, b0, th0, n);    // 8
    // layer 1
    k_gemm<true><<<gb_gemm, TB>>>(th0, W1, hh, n);
    k_gather<true><<<gb_ga, TB>>>(hh, b1, th1, n);
    // layer 2 (final: fp32 out)
    k_gemm<true><<<gb_gemm, TB>>>(th1, W2, hh, n);
    k_gather<false><<<gb_ga, TB>>>(hh, b2, out, n);
}

// round 16
// speedup vs baseline: 1.1519x; 1.1519x over previous
#include <cuda_runtime.h>
#include <cuda_fp16.h>
#include <mma.h>

using namespace nvcuda;

#define N_NODES 100000
#define MAX_E   1600000
#define D 64
#define SCAN_B 1024

struct Edge { int s; float nrm; };

// Scratch (allocation-free rule).
__device__ __align__(256) __half g_xh [N_NODES * D];  // fp16 copy of input x
__device__ __align__(256) __half g_hh [N_NODES * D];  // fp16 gemm output (gather source)
__device__ __align__(256) __half g_th0[N_NODES * D];  // fp16 relu(layer-0) activations
__device__ __align__(256) __half g_th1[N_NODES * D];  // fp16 relu(layer-1) activations
__device__ int   g_deg [N_NODES];
__device__ int   g_fill[N_NODES];
__device__ int   g_rowp[N_NODES];
__device__ float g_dinv[N_NODES];
__device__ int   g_bsum[256];
__device__ __align__(16) Edge g_csr[MAX_E];

// x(fp32) -> xh(fp16), vectorized 8 elements/thread
__global__ void k_cvt(const float* __restrict__ x, __half* __restrict__ xh, int n8) {
    int i = blockIdx.x * blockDim.x + threadIdx.x;
    if (i >= n8) return;
    const float4* x4 = (const float4*)x;
    float4 f0 = x4[i * 2], f1 = x4[i * 2 + 1];
    __half2 p0 = __floats2half2_rn(f0.x, f0.y);
    __half2 p1 = __floats2half2_rn(f0.z, f0.w);
    __half2 p2 = __floats2half2_rn(f1.x, f1.y);
    __half2 p3 = __floats2half2_rn(f1.z, f1.w);
    uint4 hv;
    hv.x = reinterpret_cast<unsigned&>(p0);
    hv.y = reinterpret_cast<unsigned&>(p1);
    hv.z = reinterpret_cast<unsigned&>(p2);
    hv.w = reinterpret_cast<unsigned&>(p3);
    ((uint4*)xh)[i] = hv;
}

__global__ void k_zero(int n) {
    int i = blockIdx.x * blockDim.x + threadIdx.x;
    if (i < n) { g_deg[i] = 0; g_fill[i] = 0; }
}

__global__ void k_count_deg(const int* __restrict__ dst, int e) {
    int i = blockIdx.x * blockDim.x + threadIdx.x;
    if (i < e) atomicAdd(&g_deg[dst[i]], 1);
}

// ---- exclusive scan of g_deg -> g_rowp ; also computes dinv (fused) ----
__global__ void k_scan_block(int n) {
    __shared__ int sm[SCAN_B];
    int t = threadIdx.x;
    int i = blockIdx.x * SCAN_B + t;
    int v = (i < n) ? g_deg[i] : 0;
    if (i < n) g_dinv[i] = rsqrtf((float)v + 1.0f);
    sm[t] = v;
    __syncthreads();
    #pragma unroll
    for (int off = 1; off < SCAN_B; off <<= 1) {
        int add = (t >= off) ? sm[t - off] : 0;
        __syncthreads();
        sm[t] += add;
        __syncthreads();
    }
    if (i < n) g_rowp[i] = sm[t] - v;
    if (t == SCAN_B - 1) g_bsum[blockIdx.x] = sm[t];
}

__global__ void k_scan_bsum(int nb) {
    if (nb > 256) nb = 256;
    int acc = 0;
    for (int b = 0; b < nb; b++) { int v = g_bsum[b]; g_bsum[b] = acc; acc += v; }
}

__global__ void k_scan_add(int n) {
    int i = blockIdx.x * blockDim.x + threadIdx.x;
    if (i < n) g_rowp[i] += g_bsum[i / SCAN_B];
}

__global__ void k_fill(const int* __restrict__ src, const int* __restrict__ dst, int e) {
    int i = blockIdx.x * blockDim.x + threadIdx.x;
    if (i >= e) return;
    int s = src[i], d = dst[i];
    int pos = g_rowp[d] + atomicAdd(&g_fill[d], 1);
    if (pos >= MAX_E) pos = MAX_E - 1;
    Edge ed; ed.s = s; ed.nrm = g_dinv[s] * g_dinv[d];
    g_csr[pos] = ed;
}

// Tensor-core GEMM: H(fp16) = A(fp16) @ W(fp32->fp16)
// 256 threads = 8 warps, 128 rows/block (16 rows/warp).
// wmma m16n16k16, 4 k-tiles x 4 n-tiles, fp32 accum staged via smem.
// ReLU is applied by the producer (gather), so this is a pure GEMM.
__global__ void __launch_bounds__(256, 2) k_gemm(
        const __half* __restrict__ A, const float* __restrict__ W,
        __half* __restrict__ Hh, int n) {
    __shared__ __half Ws[64 * 64];     // W fp16, row-major [k][c], ld=64
    __shared__ float  Os[128 * 64];    // fp32 output staging (32KB)
    int tid  = threadIdx.x;
    int warp = tid >> 5;
    int lane = tid & 31;

    // Convert W to fp16 smem (4096 elems)
    for (int i = tid; i < 4096; i += 256) Ws[i] = __float2half(W[i]);
    __syncthreads();

    int row0 = blockIdx.x * 128 + warp * 16;   // n is a multiple of 16 (100000)
    if (row0 < n) {
        wmma::fragment<wmma::accumulator, 16, 16, 16, float> acc[4];
        #pragma unroll
        for (int nt = 0; nt < 4; nt++) wmma::fill_fragment(acc[nt], 0.0f);

        #pragma unroll
        for (int kt = 0; kt < 4; kt++) {
            wmma::fragment<wmma::matrix_a, 16, 16, 16, __half, wmma::row_major> a_frag;
            wmma::load_matrix_sync(a_frag, A + (size_t)row0 * 64 + kt * 16, 64);
            #pragma unroll
            for (int nt = 0; nt < 4; nt++) {
                wmma::fragment<wmma::matrix_b, 16, 16, 16, __half, wmma::row_major> b_frag;
                wmma::load_matrix_sync(b_frag, Ws + (kt * 16) * 64 + nt * 16, 64);
                wmma::mma_sync(acc[nt], a_frag, b_frag, acc[nt]);
            }
        }
        // Stage fp32 result in smem (per-warp private region), then convert to fp16.
        float* os = Os + warp * 1024;
        #pragma unroll
        for (int nt = 0; nt < 4; nt++)
            wmma::store_matrix_sync(os + nt * 16, acc[nt], 64, wmma::mem_row_major);
        __syncwarp();

        // Flat copy: 1024 floats -> 1024 halves at Hh + row0*64 (contiguous).
        uint2* og = (uint2*)(Hh + (size_t)row0 * 64);
        const float4* of = (const float4*)os;
        #pragma unroll
        for (int i = 0; i < 8; i++) {
            float4 f = of[lane + 32 * i];
            __half2 h0 = __floats2half2_rn(f.x, f.y);
            __half2 h1 = __floats2half2_rn(f.z, f.w);
            uint2 u;
            u.x = reinterpret_cast<unsigned&>(h0);
            u.y = reinterpret_cast<unsigned&>(h1);
            og[lane + 32 * i] = u;
        }
    }
}

// CSR gather + self-loop + bias (R12 8-lane layout; best measured).
// OUT_HALF: write relu(result) as fp16 (inter-layer). Else raw fp32 (final).
template<bool OUT_HALF>
__global__ void __launch_bounds__(256) k_gather(const __half* __restrict__ Hh,
                                                const float* __restrict__ b,
                                                void* __restrict__ outv, int n) {
    int t = blockIdx.x * blockDim.x + threadIdx.x;
    int node = t >> 3;
    if (node >= n) return;
    int l = t & 7;

    int start = __ldg(&g_rowp[node]);
    int cnt   = __ldg(&g_deg[node]);
    float di  = __ldg(&g_dinv[node]);
    const Edge* ce = g_csr + start;
    const uint4* H4 = (const uint4*)Hh;

    float acc[8];
    #pragma unroll
    for (int c = 0; c < 8; c++) acc[c] = 0.0f;

    int j = 0;
    for (; j + 4 <= cnt; j += 4) {
        Edge e0 = ce[j], e1 = ce[j+1], e2 = ce[j+2], e3 = ce[j+3];
        uint4 h0 = H4[(size_t)e0.s * 8 + l];
        uint4 h1 = H4[(size_t)e1.s * 8 + l];
        uint4 h2 = H4[(size_t)e2.s * 8 + l];
        uint4 h3 = H4[(size_t)e3.s * 8 + l];
        const uint4* hv[4] = {&h0, &h1, &h2, &h3};
        float nm[4] = {e0.nrm, e1.nrm, e2.nrm, e3.nrm};
        #pragma unroll
        for (int q = 0; q < 4; q++) {
            __half2 p0 = reinterpret_cast<const __half2&>(hv[q]->x);
            __half2 p1 = reinterpret_cast<const __half2&>(hv[q]->y);
            __half2 p2 = reinterpret_cast<const __half2&>(hv[q]->z);
            __half2 p3 = reinterpret_cast<const __half2&>(hv[q]->w);
            float2 f0 = __half22float2(p0), f1 = __half22float2(p1);
            float2 f2 = __half22float2(p2), f3 = __half22float2(p3);
            acc[0] += f0.x * nm[q]; acc[1] += f0.y * nm[q];
            acc[2] += f1.x * nm[q]; acc[3] += f1.y * nm[q];
            acc[4] += f2.x * nm[q]; acc[5] += f2.y * nm[q];
            acc[6] += f3.x * nm[q]; acc[7] += f3.y * nm[q];
        }
    }
    for (; j < cnt; j++) {
        Edge cur = ce[j];
        uint4 hv = H4[(size_t)cur.s * 8 + l];
        __half2 p0 = reinterpret_cast<__half2&>(hv.x);
        __half2 p1 = reinterpret_cast<__half2&>(hv.y);
        __half2 p2 = reinterpret_cast<__half2&>(hv.z);
        __half2 p3 = reinterpret_cast<__half2&>(hv.w);
        float2 f0 = __half22float2(p0), f1 = __half22float2(p1);
        float2 f2 = __half22float2(p2), f3 = __half22float2(p3);
        float nm = cur.nrm;
        acc[0] += f0.x * nm; acc[1] += f0.y * nm;
        acc[2] += f1.x * nm; acc[3] += f1.y * nm;
        acc[4] += f2.x * nm; acc[5] += f2.y * nm;
        acc[6] += f3.x * nm; acc[7] += f3.y * nm;
    }

    // self-loop + bias
    float s = di * di;
    uint4 hv = H4[(size_t)node * 8 + l];
    __half2 p0 = reinterpret_cast<__half2&>(hv.x);
    __half2 p1 = reinterpret_cast<__half2&>(hv.y);
    __half2 p2 = reinterpret_cast<__half2&>(hv.z);
    __half2 p3 = reinterpret_cast<__half2&>(hv.w);
    float2 f0 = __half22float2(p0), f1 = __half22float2(p1);
    float2 f2 = __half22float2(p2), f3 = __half22float2(p3);
    float4 b0 = __ldg((const float4*)b + l * 2);
    float4 b1 = __ldg((const float4*)b + l * 2 + 1);

    float o0 = acc[0] + f0.x * s + b0.x, o1 = acc[1] + f0.y * s + b0.y;
    float o2 = acc[2] + f1.x * s + b0.z, o3 = acc[3] + f1.y * s + b0.w;
    float o4 = acc[4] + f2.x * s + b1.x, o5 = acc[5] + f2.y * s + b1.y;
    float o6 = acc[6] + f3.x * s + b1.z, o7 = acc[7] + f3.y * s + b1.w;

    if (OUT_HALF) {
        // Inter-layer: apply ReLU here (next GEMM consumes relu(h)).
        o0 = fmaxf(o0, 0.f); o1 = fmaxf(o1, 0.f); o2 = fmaxf(o2, 0.f); o3 = fmaxf(o3, 0.f);
        o4 = fmaxf(o4, 0.f); o5 = fmaxf(o5, 0.f); o6 = fmaxf(o6, 0.f); o7 = fmaxf(o7, 0.f);
        __half2 q0 = __floats2half2_rn(o0, o1);
        __half2 q1 = __floats2half2_rn(o2, o3);
        __half2 q2 = __floats2half2_rn(o4, o5);
        __half2 q3 = __floats2half2_rn(o6, o7);
        uint4 ov;
        ov.x = reinterpret_cast<unsigned&>(q0);
        ov.y = reinterpret_cast<unsigned&>(q1);
        ov.z = reinterpret_cast<unsigned&>(q2);
        ov.w = reinterpret_cast<unsigned&>(q3);
        ((uint4*)outv)[(size_t)node * 8 + l] = ov;
    } else {
        float4* o = (float4*)outv + (size_t)node * 16 + l * 2;
        o[0] = make_float4(o0, o1, o2, o3);
        o[1] = make_float4(o4, o5, o6, o7);
    }
}

extern "C" void kernel_launch(void* const* d_in, const int* in_sizes, int n_in,
                              void* d_out, int out_size) {
    const float* x  = (const float*)d_in[0];
    const int*   ei = (const int*)d_in[1];   // int32 (JAX x64-disabled)
    const float* W0 = (const float*)d_in[2];
    const float* b0 = (const float*)d_in[3];
    const float* W1 = (const float*)d_in[4];
    const float* b1 = (const float*)d_in[5];
    const float* W2 = (const float*)d_in[6];
    const float* b2 = (const float*)d_in[7];
    float* out = (float*)d_out;

    int n = in_sizes[0] / D;
    int e = in_sizes[1] / 2;
    const int* src = ei;
    const int* dst = ei + e;

    __half *xh, *hh, *th0, *th1;
    cudaGetSymbolAddress((void**)&xh,  g_xh);
    cudaGetSymbolAddress((void**)&hh,  g_hh);
    cudaGetSymbolAddress((void**)&th0, g_th0);
    cudaGetSymbolAddress((void**)&th1, g_th1);

    const int TB = 256;
    int n8 = n * 8;
    int gb_n    = (n + TB - 1) / TB;
    int gb_e    = (e + TB - 1) / TB;
    int gb_gemm = (n + 127) / 128;
    int gb_cvt  = (n8 + TB - 1) / TB;
    int nb_scan = (n + SCAN_B - 1) / SCAN_B;
    int gb_ga   = (n8 + TB - 1) / TB;

    k_cvt<<<gb_cvt, TB>>>(x, xh, n8);                 // 0
    k_zero<<<gb_n, TB>>>(n);                          // 1
    k_count_deg<<<gb_e, TB>>>(dst, e);                // 2
    k_gemm<<<gb_gemm, TB>>>(xh, W0, hh, n);           // 3  <- profiled (wmma)
    k_scan_block<<<nb_scan, SCAN_B>>>(n);             // 4 (also computes dinv)
    k_scan_bsum<<<1, 1>>>(nb_scan);                   // 5
    k_scan_add<<<gb_n, TB>>>(n);                      // 6
    k_fill<<<gb_e, TB>>>(src, dst, e);                // 7
    // layer 0 aggregate -> relu fp16 activations
    k_gather<true><<<gb_ga, TB>>>(hh, b0, th0, n);    // 8
    // layer 1
    k_gemm<<<gb_gemm, TB>>>(th0, W1, hh, n);
    k_gather<true><<<gb_ga, TB>>>(hh, b1, th1, n);
    // layer 2 (final: fp32 out, no relu)
    k_gemm<<<gb_gemm, TB>>>(th1, W2, hh, n);
    k_gather<false><<<gb_ga, TB>>>(hh, b2, out, n);
}

// round 17
// speedup vs baseline: 1.1873x; 1.0308x over previous
#include <cuda_runtime.h>
#include <cuda_fp16.h>
#include <mma.h>

using namespace nvcuda;

#define N_NODES 100000
#define MAX_E   1600000
#define D 64
#define SCAN_B 1024

struct Edge { int s; float nrm; };

// Scratch (allocation-free rule).
__device__ __align__(256) __half g_xh [N_NODES * D];  // fp16 copy of input x
__device__ __align__(256) __half g_hh [N_NODES * D];  // fp16 gemm output (gather source)
__device__ __align__(256) __half g_th0[N_NODES * D];  // fp16 relu(layer-0) activations
__device__ __align__(256) __half g_th1[N_NODES * D];  // fp16 relu(layer-1) activations
__device__ int   g_deg [N_NODES];
__device__ int   g_fill[N_NODES];
__device__ int   g_rowp[N_NODES];
__device__ float g_dinv[N_NODES];
__device__ int   g_bsum[256];
__device__ __align__(16) Edge g_csr[MAX_E];

// x(fp32) -> xh(fp16), vectorized 8 elements/thread
__global__ void k_cvt(const float* __restrict__ x, __half* __restrict__ xh, int n8) {
    int i = blockIdx.x * blockDim.x + threadIdx.x;
    if (i >= n8) return;
    const float4* x4 = (const float4*)x;
    float4 f0 = x4[i * 2], f1 = x4[i * 2 + 1];
    __half2 p0 = __floats2half2_rn(f0.x, f0.y);
    __half2 p1 = __floats2half2_rn(f0.z, f0.w);
    __half2 p2 = __floats2half2_rn(f1.x, f1.y);
    __half2 p3 = __floats2half2_rn(f1.z, f1.w);
    uint4 hv;
    hv.x = reinterpret_cast<unsigned&>(p0);
    hv.y = reinterpret_cast<unsigned&>(p1);
    hv.z = reinterpret_cast<unsigned&>(p2);
    hv.w = reinterpret_cast<unsigned&>(p3);
    ((uint4*)xh)[i] = hv;
}

__global__ void k_zero(int n) {
    int i = blockIdx.x * blockDim.x + threadIdx.x;
    if (i < n) { g_deg[i] = 0; g_fill[i] = 0; }
}

__global__ void k_count_deg(const int* __restrict__ dst, int e) {
    int i = blockIdx.x * blockDim.x + threadIdx.x;
    if (i < e) atomicAdd(&g_deg[dst[i]], 1);
}

// ---- exclusive scan of g_deg -> g_rowp ; also computes dinv (fused) ----
__global__ void k_scan_block(int n) {
    __shared__ int sm[SCAN_B];
    int t = threadIdx.x;
    int i = blockIdx.x * SCAN_B + t;
    int v = (i < n) ? g_deg[i] : 0;
    if (i < n) g_dinv[i] = rsqrtf((float)v + 1.0f);
    sm[t] = v;
    __syncthreads();
    #pragma unroll
    for (int off = 1; off < SCAN_B; off <<= 1) {
        int add = (t >= off) ? sm[t - off] : 0;
        __syncthreads();
        sm[t] += add;
        __syncthreads();
    }
    if (i < n) g_rowp[i] = sm[t] - v;
    if (t == SCAN_B - 1) g_bsum[blockIdx.x] = sm[t];
}

__global__ void k_scan_bsum(int nb) {
    if (nb > 256) nb = 256;
    int acc = 0;
    for (int b = 0; b < nb; b++) { int v = g_bsum[b]; g_bsum[b] = acc; acc += v; }
}

__global__ void k_scan_add(int n) {
    int i = blockIdx.x * blockDim.x + threadIdx.x;
    if (i < n) g_rowp[i] += g_bsum[i / SCAN_B];
}

__global__ void k_fill(const int* __restrict__ src, const int* __restrict__ dst, int e) {
    int i = blockIdx.x * blockDim.x + threadIdx.x;
    if (i >= e) return;
    int s = src[i], d = dst[i];
    int pos = g_rowp[d] + atomicAdd(&g_fill[d], 1);
    if (pos >= MAX_E) pos = MAX_E - 1;
    Edge ed; ed.s = s; ed.nrm = g_dinv[s] * g_dinv[d];
    g_csr[pos] = ed;
}

// Tensor-core GEMM: H(fp16) = A(fp16) @ W(fp32->fp16)
// 256 threads = 8 warps, 128 rows/block (16 rows/warp, n % 16 == 0).
// All 4 a_frags loaded upfront (MLP=4), fp32 accum converted in registers,
// stored directly as fp16 (no smem staging; smem = 8KB for W only).
__global__ void __launch_bounds__(256) k_gemm(
        const __half* __restrict__ A, const float* __restrict__ W,
        __half* __restrict__ Hh, int n) {
    __shared__ __half Ws[64 * 64];     // W fp16, row-major [k][c], ld=64
    int tid  = threadIdx.x;
    int warp = tid >> 5;

    for (int i = tid; i < 4096; i += 256) Ws[i] = __float2half(W[i]);
    __syncthreads();

    int row0 = blockIdx.x * 128 + warp * 16;
    if (row0 >= n) return;

    // Issue all global A loads first — 4 independent 16x16 fragments.
    wmma::fragment<wmma::matrix_a, 16, 16, 16, __half, wmma::row_major> a_frag[4];
    #pragma unroll
    for (int kt = 0; kt < 4; kt++)
        wmma::load_matrix_sync(a_frag[kt], A + (size_t)row0 * 64 + kt * 16, 64);

    wmma::fragment<wmma::accumulator, 16, 16, 16, float> acc[4];
    #pragma unroll
    for (int nt = 0; nt < 4; nt++) wmma::fill_fragment(acc[nt], 0.0f);

    #pragma unroll
    for (int kt = 0; kt < 4; kt++) {
        #pragma unroll
        for (int nt = 0; nt < 4; nt++) {
            wmma::fragment<wmma::matrix_b, 16, 16, 16, __half, wmma::row_major> b_frag;
            wmma::load_matrix_sync(b_frag, Ws + (kt * 16) * 64 + nt * 16, 64);
            wmma::mma_sync(acc[nt], a_frag[kt], b_frag, acc[nt]);
        }
    }

    // Convert fp32 accum -> fp16 in registers, store directly.
    #pragma unroll
    for (int nt = 0; nt < 4; nt++) {
        wmma::fragment<wmma::accumulator, 16, 16, 16, __half> hacc;
        #pragma unroll
        for (int i = 0; i < hacc.num_elements; i++)
            hacc.x[i] = __float2half(acc[nt].x[i]);
        wmma::store_matrix_sync(Hh + (size_t)row0 * 64 + nt * 16, hacc, 64,
                                wmma::mem_row_major);
    }
}

// CSR gather + self-loop + bias (8-lane layout; best measured).
// OUT_HALF: write relu(result) as fp16 (inter-layer). Else raw fp32 (final).
template<bool OUT_HALF>
__global__ void __launch_bounds__(256) k_gather(const __half* __restrict__ Hh,
                                                const float* __restrict__ b,
                                                void* __restrict__ outv, int n) {
    int t = blockIdx.x * blockDim.x + threadIdx.x;
    int node = t >> 3;
    if (node >= n) return;
    int l = t & 7;

    int start = __ldg(&g_rowp[node]);
    int cnt   = __ldg(&g_deg[node]);
    float di  = __ldg(&g_dinv[node]);
    const Edge* ce = g_csr + start;
    const uint4* H4 = (const uint4*)Hh;

    float acc[8];
    #pragma unroll
    for (int c = 0; c < 8; c++) acc[c] = 0.0f;

    int j = 0;
    for (; j + 4 <= cnt; j += 4) {
        Edge e0 = ce[j], e1 = ce[j+1], e2 = ce[j+2], e3 = ce[j+3];
        uint4 h0 = H4[(size_t)e0.s * 8 + l];
        uint4 h1 = H4[(size_t)e1.s * 8 + l];
        uint4 h2 = H4[(size_t)e2.s * 8 + l];
        uint4 h3 = H4[(size_t)e3.s * 8 + l];
        const uint4* hv[4] = {&h0, &h1, &h2, &h3};
        float nm[4] = {e0.nrm, e1.nrm, e2.nrm, e3.nrm};
        #pragma unroll
        for (int q = 0; q < 4; q++) {
            __half2 p0 = reinterpret_cast<const __half2&>(hv[q]->x);
            __half2 p1 = reinterpret_cast<const __half2&>(hv[q]->y);
            __half2 p2 = reinterpret_cast<const __half2&>(hv[q]->z);
            __half2 p3 = reinterpret_cast<const __half2&>(hv[q]->w);
            float2 f0 = __half22float2(p0), f1 = __half22float2(p1);
            float2 f2 = __half22float2(p2), f3 = __half22float2(p3);
            acc[0] += f0.x * nm[q]; acc[1] += f0.y * nm[q];
            acc[2] += f1.x * nm[q]; acc[3] += f1.y * nm[q];
            acc[4] += f2.x * nm[q]; acc[5] += f2.y * nm[q];
            acc[6] += f3.x * nm[q]; acc[7] += f3.y * nm[q];
        }
    }
    for (; j < cnt; j++) {
        Edge cur = ce[j];
        uint4 hv = H4[(size_t)cur.s * 8 + l];
        __half2 p0 = reinterpret_cast<__half2&>(hv.x);
        __half2 p1 = reinterpret_cast<__half2&>(hv.y);
        __half2 p2 = reinterpret_cast<__half2&>(hv.z);
        __half2 p3 = reinterpret_cast<__half2&>(hv.w);
        float2 f0 = __half22float2(p0), f1 = __half22float2(p1);
        float2 f2 = __half22float2(p2), f3 = __half22float2(p3);
        float nm = cur.nrm;
        acc[0] += f0.x * nm; acc[1] += f0.y * nm;
        acc[2] += f1.x * nm; acc[3] += f1.y * nm;
        acc[4] += f2.x * nm; acc[5] += f2.y * nm;
        acc[6] += f3.x * nm; acc[7] += f3.y * nm;
    }

    // self-loop + bias
    float s = di * di;
    uint4 hv = H4[(size_t)node * 8 + l];
    __half2 p0 = reinterpret_cast<__half2&>(hv.x);
    __half2 p1 = reinterpret_cast<__half2&>(hv.y);
    __half2 p2 = reinterpret_cast<__half2&>(hv.z);
    __half2 p3 = reinterpret_cast<__half2&>(hv.w);
    float2 f0 = __half22float2(p0), f1 = __half22float2(p1);
    float2 f2 = __half22float2(p2), f3 = __half22float2(p3);
    float4 b0 = __ldg((const float4*)b + l * 2);
    float4 b1 = __ldg((const float4*)b + l * 2 + 1);

    float o0 = acc[0] + f0.x * s + b0.x, o1 = acc[1] + f0.y * s + b0.y;
    float o2 = acc[2] + f1.x * s + b0.z, o3 = acc[3] + f1.y * s + b0.w;
    float o4 = acc[4] + f2.x * s + b1.x, o5 = acc[5] + f2.y * s + b1.y;
    float o6 = acc[6] + f3.x * s + b1.z, o7 = acc[7] + f3.y * s + b1.w;

    if (OUT_HALF) {
        // Inter-layer: apply ReLU here (next GEMM consumes relu(h)).
        o0 = fmaxf(o0, 0.f); o1 = fmaxf(o1, 0.f); o2 = fmaxf(o2, 0.f); o3 = fmaxf(o3, 0.f);
        o4 = fmaxf(o4, 0.f); o5 = fmaxf(o5, 0.f); o6 = fmaxf(o6, 0.f); o7 = fmaxf(o7, 0.f);
        __half2 q0 = __floats2half2_rn(o0, o1);
        __half2 q1 = __floats2half2_rn(o2, o3);
        __half2 q2 = __floats2half2_rn(o4, o5);
        __half2 q3 = __floats2half2_rn(o6, o7);
        uint4 ov;
        ov.x = reinterpret_cast<unsigned&>(q0);
        ov.y = reinterpret_cast<unsigned&>(q1);
        ov.z = reinterpret_cast<unsigned&>(q2);
        ov.w = reinterpret_cast<unsigned&>(q3);
        ((uint4*)outv)[(size_t)node * 8 + l] = ov;
    } else {
        float4* o = (float4*)outv + (size_t)node * 16 + l * 2;
        o[0] = make_float4(o0, o1, o2, o3);
        o[1] = make_float4(o4, o5, o6, o7);
    }
}

extern "C" void kernel_launch(void* const* d_in, const int* in_sizes, int n_in,
                              void* d_out, int out_size) {
    const float* x  = (const float*)d_in[0];
    const int*   ei = (const int*)d_in[1];   // int32 (JAX x64-disabled)
    const float* W0 = (const float*)d_in[2];
    const float* b0 = (const float*)d_in[3];
    const float* W1 = (const float*)d_in[4];
    const float* b1 = (const float*)d_in[5];
    const float* W2 = (const float*)d_in[6];
    const float* b2 = (const float*)d_in[7];
    float* out = (float*)d_out;

    int n = in_sizes[0] / D;
    int e = in_sizes[1] / 2;
    const int* src = ei;
    const int* dst = ei + e;

    __half *xh, *hh, *th0, *th1;
    cudaGetSymbolAddress((void**)&xh,  g_xh);
    cudaGetSymbolAddress((void**)&hh,  g_hh);
    cudaGetSymbolAddress((void**)&th0, g_th0);
    cudaGetSymbolAddress((void**)&th1, g_th1);

    const int TB = 256;
    int n8 = n * 8;
    int gb_n    = (n + TB - 1) / TB;
    int gb_e    = (e + TB - 1) / TB;
    int gb_gemm = (n + 127) / 128;
    int gb_cvt  = (n8 + TB - 1) / TB;
    int nb_scan = (n + SCAN_B - 1) / SCAN_B;
    int gb_ga   = (n8 + TB - 1) / TB;

    k_cvt<<<gb_cvt, TB>>>(x, xh, n8);                 // 0
    k_zero<<<gb_n, TB>>>(n);                          // 1
    k_count_deg<<<gb_e, TB>>>(dst, e);                // 2
    k_gemm<<<gb_gemm, TB>>>(xh, W0, hh, n);           // 3  <- profiled (wmma)
    k_scan_block<<<nb_scan, SCAN_B>>>(n);             // 4 (also computes dinv)
    k_scan_bsum<<<1, 1>>>(nb_scan);                   // 5
    k_scan_add<<<gb_n, TB>>>(n);                      // 6
    k_fill<<<gb_e, TB>>>(src, dst, e);                // 7
    // layer 0 aggregate -> relu fp16 activations
    k_gather<true><<<gb_ga, TB>>>(hh, b0, th0, n);    // 8
    // layer 1
    k_gemm<<<gb_gemm, TB>>>(th0, W1, hh, n);
    k_gather<true><<<gb_ga, TB>>>(hh, b1, th1, n);
    // layer 2 (final: fp32 out, no relu)
    k_gemm<<<gb_gemm, TB>>>(th1, W2, hh, n);
    k_gather<false><<<gb_ga, TB>>>(hh, b2, out, n);
}